// round 13
// baseline (speedup 1.0000x reference)
#include <cuda_runtime.h>
#include <math.h>

#define T_   40
#define B_   64
#define TB_  2560      // T*B
#define KDIM 512       // all GEMM K dims are 512 (E == 2H)

typedef unsigned long long ull;

// ---------------- packed f32x2 helpers (sm_100+) ----------------
__device__ __forceinline__ void ffma2(ull &d, ull a, ull b) {
    asm("fma.rn.f32x2 %0, %1, %2, %0;" : "+l"(d) : "l"(a), "l"(b));
}
__device__ __forceinline__ ull dup2(float x) {
    ull r; asm("mov.b64 %0, {%1, %1};" : "=l"(r) : "f"(x)); return r;
}
__device__ __forceinline__ float2 unpk(ull v) {
    float2 r; asm("mov.b64 {%0, %1}, %2;" : "=f"(r.x), "=f"(r.y) : "l"(v)); return r;
}

// ---------------- device scratch (no allocations allowed) ----------------
__device__ float g_x[TB_ * 512];
__device__ float g_y[TB_ * 512];
__device__ float g_xgA[TB_ * 1024];       // encoder fwd xg
__device__ float g_xgB[TB_ * 1024];       // encoder bwd xg
__device__ float g_xgD[TB_ * 2048];       // decoder xg
__device__ float g_encH[2][2 * B_ * 256]; // ping-pong h: [buf][dir][b][256]
__device__ float g_encC[2 * B_ * 256];
__device__ float g_decH[2][B_ * 512];
__device__ float g_decC[B_ * 512];
__device__ float g_hf[2][B_ * 512];       // encoder finals per layer (concat fwd,bwd)
__device__ float g_cf[2][B_ * 512];

// ---------------- embedding gather ----------------
__global__ void embed_kernel(const int* __restrict__ tok,
                             const float* __restrict__ emb,
                             float* __restrict__ out) {
    int row = blockIdx.x;                 // 0..TB_-1
    int t = tok[row];
    const float4* s = reinterpret_cast<const float4*>(emb + (size_t)t * 512);
    float4* d = reinterpret_cast<float4*>(out + (size_t)row * 512);
    d[threadIdx.x] = s[threadIdx.x];      // 128 threads * float4 = 512 floats
}

__global__ void zero2_kernel(float* a, float* b, int n) {
    int i = blockIdx.x * blockDim.x + threadIdx.x;
    if (i < n) { a[i] = 0.f; b[i] = 0.f; }
}
__global__ void copy2_kernel(float* da, const float* sa, float* db, const float* sb, int n) {
    int i = blockIdx.x * blockDim.x + threadIdx.x;
    if (i < n) { da[i] = sa[i]; db[i] = sb[i]; }
}
// encoder h/c [dir][b][256] -> finals [b][dir*256 + u]
__global__ void save_finals_kernel(const float* __restrict__ h, const float* __restrict__ c,
                                   float* __restrict__ hf, float* __restrict__ cf) {
    int i = blockIdx.x * blockDim.x + threadIdx.x;      // 2*64*256
    if (i >= 2 * B_ * 256) return;
    int dir = i / (B_ * 256);
    int rem = i - dir * (B_ * 256);
    int b = rem / 256, u = rem - b * 256;
    hf[b * 512 + dir * 256 + u] = h[i];
    cf[b * 512 + dir * 256 + u] = c[i];
}

// ---------------- fp32 GEMM with packed f32x2 FMA ----------------
// C[M,N] = A[M,512] * W[N,512]^T + bias[N]
// 128x128 tile, BK=16, 256 threads, 8x8 microtile (4+4 split rows/cols)
__global__ __launch_bounds__(256) void gemm_bias_kernel(
    const float* __restrict__ A, const float* __restrict__ W,
    const float* __restrict__ bias, float* __restrict__ C,
    int M, int N) {
    __shared__ __align__(16) float As[16][128];
    __shared__ __align__(16) float Bs[16][128];

    const int tid = threadIdx.x;
    const int tx = tid & 15;
    const int ty = tid >> 4;
    const int rowBase = blockIdx.y * 128;
    const int colBase = blockIdx.x * 128;
    const int lrow = tid >> 2;            // 0..63
    const int lk = (tid & 3) * 4;         // 0,4,8,12

    const float* Ap = A + (size_t)(rowBase + lrow) * KDIM + lk;
    const float* Wp = W + (size_t)(colBase + lrow) * KDIM + lk;

    float4 ar0 = *(const float4*)Ap;
    float4 ar1 = *(const float4*)(Ap + 64 * KDIM);
    float4 br0 = *(const float4*)Wp;
    float4 br1 = *(const float4*)(Wp + 64 * KDIM);

    ull acc[8][4];
#pragma unroll
    for (int i = 0; i < 8; i++)
#pragma unroll
        for (int j = 0; j < 4; j++) acc[i][j] = 0ull;

    const int NKB = KDIM / 16;
    for (int kb = 0; kb < NKB; kb++) {
        __syncthreads();
        As[lk + 0][lrow]      = ar0.x; As[lk + 1][lrow]      = ar0.y;
        As[lk + 2][lrow]      = ar0.z; As[lk + 3][lrow]      = ar0.w;
        As[lk + 0][lrow + 64] = ar1.x; As[lk + 1][lrow + 64] = ar1.y;
        As[lk + 2][lrow + 64] = ar1.z; As[lk + 3][lrow + 64] = ar1.w;
        Bs[lk + 0][lrow]      = br0.x; Bs[lk + 1][lrow]      = br0.y;
        Bs[lk + 2][lrow]      = br0.z; Bs[lk + 3][lrow]      = br0.w;
        Bs[lk + 0][lrow + 64] = br1.x; Bs[lk + 1][lrow + 64] = br1.y;
        Bs[lk + 2][lrow + 64] = br1.z; Bs[lk + 3][lrow + 64] = br1.w;
        __syncthreads();
        if (kb + 1 < NKB) {              // prefetch next k-block into registers
            const float* Apn = Ap + (kb + 1) * 16;
            const float* Wpn = Wp + (kb + 1) * 16;
            ar0 = *(const float4*)Apn;
            ar1 = *(const float4*)(Apn + 64 * KDIM);
            br0 = *(const float4*)Wpn;
            br1 = *(const float4*)(Wpn + 64 * KDIM);
        }
#pragma unroll
        for (int k = 0; k < 16; k++) {
            float4 a0 = *(const float4*)(&As[k][ty * 4]);
            float4 a1 = *(const float4*)(&As[k][64 + ty * 4]);
            ulonglong2 b0 = *(const ulonglong2*)(&Bs[k][tx * 4]);
            ulonglong2 b1 = *(const ulonglong2*)(&Bs[k][64 + tx * 4]);
            ull ad[8];
            ad[0] = dup2(a0.x); ad[1] = dup2(a0.y); ad[2] = dup2(a0.z); ad[3] = dup2(a0.w);
            ad[4] = dup2(a1.x); ad[5] = dup2(a1.y); ad[6] = dup2(a1.z); ad[7] = dup2(a1.w);
#pragma unroll
            for (int i = 0; i < 8; i++) {
                ffma2(acc[i][0], ad[i], b0.x);
                ffma2(acc[i][1], ad[i], b0.y);
                ffma2(acc[i][2], ad[i], b1.x);
                ffma2(acc[i][3], ad[i], b1.y);
            }
        }
    }

    float4 bs0 = *(const float4*)(bias + colBase + tx * 4);
    float4 bs1 = *(const float4*)(bias + colBase + 64 + tx * 4);
#pragma unroll
    for (int i = 0; i < 8; i++) {
        int row = rowBase + (i < 4 ? ty * 4 + i : 64 + ty * 4 + (i - 4));
        float2 p0 = unpk(acc[i][0]);
        float2 p1 = unpk(acc[i][1]);
        float2 p2 = unpk(acc[i][2]);
        float2 p3 = unpk(acc[i][3]);
        float4 v0 = make_float4(p0.x + bs0.x, p0.y + bs0.y, p1.x + bs0.z, p1.y + bs0.w);
        float4 v1 = make_float4(p2.x + bs1.x, p2.y + bs1.y, p3.x + bs1.z, p3.y + bs1.w);
        *(float4*)(C + (size_t)row * N + colBase + tx * 4)      = v0;
        *(float4*)(C + (size_t)row * N + colBase + 64 + tx * 4) = v1;
    }
}

// ---------------- fused LSTM step ----------------
// One time step: g = xg[t] + h_in @ Whh^T + bhh ; gate order i,f,g,o.
// Writes h_out, c (in place), y[t, :, dir*HC .. dir*HC+HC).
// grid: (HC/8, B/16, ndir), 128 threads; thread owns (batch bl, unit ul).
template <int HC>
__global__ __launch_bounds__(128) void lstm_step_kernel(
    const float* __restrict__ xg0, const float* __restrict__ xg1,
    const float* __restrict__ Whh, const float* __restrict__ bhh,
    const float* __restrict__ h_in, float* __restrict__ h_out,
    float* __restrict__ c, float* __restrict__ y, int s) {
    const int dir = blockIdx.z;
    const int t = (dir == 0) ? s : (T_ - 1 - s);
    const float* xg = (dir == 0) ? xg0 : xg1;
    const float* W  = Whh + (size_t)dir * 4 * HC * HC;
    const float* bb = bhh + dir * 4 * HC;
    const float* hi = h_in + (size_t)dir * B_ * HC;
    float* ho = h_out + (size_t)dir * B_ * HC;
    float* cp = c + (size_t)dir * B_ * HC;

    const int tid = threadIdx.x;
    const int b0 = blockIdx.y * 16;
    const int u0 = blockIdx.x * 8;
    const int bl = tid & 15;
    const int ul = tid >> 4;
    const int b = b0 + bl;
    const int u = u0 + ul;

    __shared__ __align__(16) float h_sh[16][HC + 4];
    for (int i = tid; i < 16 * (HC / 4); i += 128) {
        int r = i / (HC / 4), kq = i - r * (HC / 4);
        float4 v = *(const float4*)(hi + (size_t)(b0 + r) * HC + kq * 4);
        *(float4*)(&h_sh[r][kq * 4]) = v;
    }
    __syncthreads();

    const float* w0 = W + (size_t)(0 * HC + u) * HC;
    const float* w1 = W + (size_t)(1 * HC + u) * HC;
    const float* w2 = W + (size_t)(2 * HC + u) * HC;
    const float* w3 = W + (size_t)(3 * HC + u) * HC;
    float a0 = 0.f, a1 = 0.f, a2 = 0.f, a3 = 0.f;
#pragma unroll 8
    for (int k = 0; k < HC; k += 4) {
        float4 hv = *(const float4*)(&h_sh[bl][k]);
        float4 v0 = __ldg((const float4*)(w0 + k));
        float4 v1 = __ldg((const float4*)(w1 + k));
        float4 v2 = __ldg((const float4*)(w2 + k));
        float4 v3 = __ldg((const float4*)(w3 + k));
        a0 += hv.x * v0.x + hv.y * v0.y + hv.z * v0.z + hv.w * v0.w;
        a1 += hv.x * v1.x + hv.y * v1.y + hv.z * v1.z + hv.w * v1.w;
        a2 += hv.x * v2.x + hv.y * v2.y + hv.z * v2.z + hv.w * v2.w;
        a3 += hv.x * v3.x + hv.y * v3.y + hv.z * v3.z + hv.w * v3.w;
    }
    const float* xrow = xg + ((size_t)t * B_ + b) * 4 * HC;
    float gi = xrow[0 * HC + u] + a0 + bb[0 * HC + u];
    float gf = xrow[1 * HC + u] + a1 + bb[1 * HC + u];
    float gg = xrow[2 * HC + u] + a2 + bb[2 * HC + u];
    float go = xrow[3 * HC + u] + a3 + bb[3 * HC + u];
    float ii = 1.f / (1.f + expf(-gi));
    float ff = 1.f / (1.f + expf(-gf));
    float oo = 1.f / (1.f + expf(-go));
    size_t ci = (size_t)b * HC + u;
    float cn = ff * cp[ci] + ii * tanhf(gg);
    float hn = oo * tanhf(cn);
    cp[ci] = cn;
    ho[ci] = hn;
    y[((size_t)t * B_ + b) * 512 + dir * HC + u] = hn;
}

static inline void launch_gemm(const float* A, const float* W, const float* bias,
                               float* C, int M, int N) {
    dim3 g(N / 128, M / 128), bl(256);
    gemm_bias_kernel<<<g, bl>>>(A, W, bias, C, M, N);
}

extern "C" void kernel_launch(void* const* d_in, const int* in_sizes, int n_in,
                              void* d_out, int out_size) {
    (void)in_sizes; (void)n_in; (void)out_size;
    const int*   src      = (const int*)  d_in[0];
    const int*   tgt      = (const int*)  d_in[1];
    const float* src_emb  = (const float*)d_in[2];
    const float* tgt_emb  = (const float*)d_in[3];
    const float* enc_Wih  = (const float*)d_in[4];   // [2,2,1024,512]
    const float* enc_Whh  = (const float*)d_in[5];   // [2,2,1024,256]
    const float* enc_bih  = (const float*)d_in[6];   // [2,2,1024]
    const float* enc_bhh  = (const float*)d_in[7];   // [2,2,1024]
    const float* dec_Wih  = (const float*)d_in[8];   // [2,2048,512]
    const float* dec_Whh  = (const float*)d_in[9];   // [2,2048,512]
    const float* dec_bih  = (const float*)d_in[10];  // [2,2048]
    const float* dec_bhh  = (const float*)d_in[11];  // [2,2048]
    const float* lin_W    = (const float*)d_in[12];  // [32000,512]
    const float* lin_b    = (const float*)d_in[13];  // [32000]
    float* logits = (float*)d_out;

    float *xA, *xB, *hA, *cA, *hfA, *cfA;
    cudaGetSymbolAddress((void**)&xA,  g_x);
    cudaGetSymbolAddress((void**)&xB,  g_y);
    cudaGetSymbolAddress((void**)&hA,  g_encH);
    cudaGetSymbolAddress((void**)&cA,  g_encC);
    cudaGetSymbolAddress((void**)&hfA, g_hf);
    cudaGetSymbolAddress((void**)&cfA, g_cf);
    float *xgA, *xgB, *xgD, *dH, *dC;
    cudaGetSymbolAddress((void**)&xgA, g_xgA);
    cudaGetSymbolAddress((void**)&xgB, g_xgB);
    cudaGetSymbolAddress((void**)&xgD, g_xgD);
    cudaGetSymbolAddress((void**)&dH,  g_decH);
    cudaGetSymbolAddress((void**)&dC,  g_decC);

    const int ENC_STATE = 2 * B_ * 256;     // 32768 per buffer
    const int DEC_STATE = B_ * 512;         // 32768

    // ---- source embedding ----
    embed_kernel<<<TB_, 128>>>(src, src_emb, xA);

    // ---- encoder: 2 stacked bidirectional layers ----
    float* ein = xA;
    float* eout = xB;
    for (int l = 0; l < 2; l++) {
        const float* Wih = enc_Wih + (size_t)l * 2 * 1024 * 512;
        const float* Whh = enc_Whh + (size_t)l * 2 * 1024 * 256;
        const float* bih = enc_bih + (size_t)l * 2 * 1024;
        const float* bhh = enc_bhh + (size_t)l * 2 * 1024;
        launch_gemm(ein, Wih,                  bih,        xgA, TB_, 1024);
        launch_gemm(ein, Wih + 1024 * 512,     bih + 1024, xgB, TB_, 1024);
        zero2_kernel<<<(ENC_STATE + 255) / 256, 256>>>(hA, cA, ENC_STATE);
        for (int s = 0; s < T_; s++) {
            float* hin  = hA + (size_t)(s & 1) * ENC_STATE;
            float* hout = hA + (size_t)((s + 1) & 1) * ENC_STATE;
            dim3 g(256 / 8, B_ / 16, 2);
            lstm_step_kernel<256><<<g, 128>>>(xgA, xgB, Whh, bhh, hin, hout, cA, eout, s);
        }
        // after T_=40 steps (even), final h is in buffer 0
        save_finals_kernel<<<(ENC_STATE + 255) / 256, 256>>>(
            hA, cA, hfA + (size_t)l * DEC_STATE, cfA + (size_t)l * DEC_STATE);
        float* tmp = ein; ein = eout; eout = tmp;
    }

    // ---- target embedding (reuse the now-free buffer) ----
    float* din = eout;   // after swap, eout is the stale buffer -> reuse as decoder input
    float* dout = ein;   // holds last encoder y (only finals needed) -> reuse as output
    embed_kernel<<<TB_, 128>>>(tgt, tgt_emb, din);

    // ---- decoder: 2 stacked layers, hidden 512 ----
    for (int l = 0; l < 2; l++) {
        const float* Wih = dec_Wih + (size_t)l * 2048 * 512;
        const float* Whh = dec_Whh + (size_t)l * 2048 * 512;
        const float* bih = dec_bih + (size_t)l * 2048;
        const float* bhh = dec_bhh + (size_t)l * 2048;
        launch_gemm(din, Wih, bih, xgD, TB_, 2048);
        copy2_kernel<<<(DEC_STATE + 255) / 256, 256>>>(
            dH, hfA + (size_t)l * DEC_STATE, dC, cfA + (size_t)l * DEC_STATE, DEC_STATE);
        for (int s = 0; s < T_; s++) {
            float* hin  = dH + (size_t)(s & 1) * DEC_STATE;
            float* hout = dH + (size_t)((s + 1) & 1) * DEC_STATE;
            dim3 g(512 / 8, B_ / 16, 1);
            lstm_step_kernel<512><<<g, 128>>>(xgD, xgD, Whh, bhh, hin, hout, dC, dout, s);
        }
        float* tmp = din; din = dout; dout = tmp;
    }

    // ---- final projection: logits[2560,32000] = y @ lin_W^T + lin_b ----
    launch_gemm(din, lin_W, lin_b, logits, TB_, 32000);
}

// round 14
// speedup vs baseline: 1.1729x; 1.1729x over previous
#include <cuda_runtime.h>
#include <math.h>

#define T_   40
#define B_   64
#define TB_  2560      // T*B
#define KDIM 512       // all GEMM K dims are 512 (E == 2H)
#define GRID_P 128     // persistent grid size (<= SM count; all co-resident)

typedef unsigned long long ull;

// ---------------- packed f32x2 helpers (sm_100+) ----------------
__device__ __forceinline__ void ffma2(ull &d, ull a, ull b) {
    asm("fma.rn.f32x2 %0, %1, %2, %0;" : "+l"(d) : "l"(a), "l"(b));
}
__device__ __forceinline__ ull dup2(float x) {
    ull r; asm("mov.b64 %0, {%1, %1};" : "=l"(r) : "f"(x)); return r;
}
__device__ __forceinline__ float2 unpk(ull v) {
    float2 r; asm("mov.b64 {%0, %1}, %2;" : "=f"(r.x), "=f"(r.y) : "l"(v)); return r;
}

// ---------------- device scratch (no allocations allowed) ----------------
__device__ float g_x[TB_ * 512];
__device__ float g_y[TB_ * 512];
__device__ float g_xgA[TB_ * 1024];       // encoder fwd xg
__device__ float g_xgB[TB_ * 1024];       // encoder bwd xg
__device__ float g_xgD[TB_ * 2048];       // decoder xg
__device__ float g_hbuf[2][B_ * 512];     // ping-pong h (enc: [dir][b][256]; dec: [b][512])
__device__ float g_hf[2][B_ * 512];       // encoder finals per layer (concat fwd,bwd)
__device__ float g_cf[2][B_ * 512];
__device__ unsigned g_bar_cnt;            // grid barrier state (zero-init)
__device__ unsigned g_bar_gen;

// ---------------- grid-wide barrier (all GRID_P blocks co-resident) ------
__device__ __forceinline__ void grid_bar() {
    __threadfence();
    __syncthreads();
    if (threadIdx.x == 0) {
        unsigned gen = *((volatile unsigned*)&g_bar_gen);
        unsigned t = atomicAdd(&g_bar_cnt, 1u);
        if (t == GRID_P - 1) {
            g_bar_cnt = 0;
            __threadfence();
            *((volatile unsigned*)&g_bar_gen) = gen + 1;
        } else {
            while (*((volatile unsigned*)&g_bar_gen) == gen) { __nanosleep(32); }
        }
    }
    __syncthreads();
}

// ---------------- embedding gather ----------------
__global__ void embed_kernel(const int* __restrict__ tok,
                             const float* __restrict__ emb,
                             float* __restrict__ out) {
    int row = blockIdx.x;                 // 0..TB_-1
    int t = tok[row];
    const float4* s = reinterpret_cast<const float4*>(emb + (size_t)t * 512);
    float4* d = reinterpret_cast<float4*>(out + (size_t)row * 512);
    d[threadIdx.x] = s[threadIdx.x];      // 128 threads * float4 = 512 floats
}

// ---------------- fp32 GEMM with packed f32x2 FMA ----------------
// C[M,N] = A[M,512] * W[N,512]^T + bias[N]
__global__ __launch_bounds__(256) void gemm_bias_kernel(
    const float* __restrict__ A, const float* __restrict__ W,
    const float* __restrict__ bias, float* __restrict__ C,
    int M, int N) {
    __shared__ __align__(16) float As[16][128];
    __shared__ __align__(16) float Bs[16][128];

    const int tid = threadIdx.x;
    const int tx = tid & 15;
    const int ty = tid >> 4;
    const int rowBase = blockIdx.y * 128;
    const int colBase = blockIdx.x * 128;
    const int lrow = tid >> 2;            // 0..63
    const int lk = (tid & 3) * 4;         // 0,4,8,12

    const float* Ap = A + (size_t)(rowBase + lrow) * KDIM + lk;
    const float* Wp = W + (size_t)(colBase + lrow) * KDIM + lk;

    float4 ar0 = *(const float4*)Ap;
    float4 ar1 = *(const float4*)(Ap + 64 * KDIM);
    float4 br0 = *(const float4*)Wp;
    float4 br1 = *(const float4*)(Wp + 64 * KDIM);

    ull acc[8][4];
#pragma unroll
    for (int i = 0; i < 8; i++)
#pragma unroll
        for (int j = 0; j < 4; j++) acc[i][j] = 0ull;

    const int NKB = KDIM / 16;
    for (int kb = 0; kb < NKB; kb++) {
        __syncthreads();
        As[lk + 0][lrow]      = ar0.x; As[lk + 1][lrow]      = ar0.y;
        As[lk + 2][lrow]      = ar0.z; As[lk + 3][lrow]      = ar0.w;
        As[lk + 0][lrow + 64] = ar1.x; As[lk + 1][lrow + 64] = ar1.y;
        As[lk + 2][lrow + 64] = ar1.z; As[lk + 3][lrow + 64] = ar1.w;
        Bs[lk + 0][lrow]      = br0.x; Bs[lk + 1][lrow]      = br0.y;
        Bs[lk + 2][lrow]      = br0.z; Bs[lk + 3][lrow]      = br0.w;
        Bs[lk + 0][lrow + 64] = br1.x; Bs[lk + 1][lrow + 64] = br1.y;
        Bs[lk + 2][lrow + 64] = br1.z; Bs[lk + 3][lrow + 64] = br1.w;
        __syncthreads();
        if (kb + 1 < NKB) {
            const float* Apn = Ap + (kb + 1) * 16;
            const float* Wpn = Wp + (kb + 1) * 16;
            ar0 = *(const float4*)Apn;
            ar1 = *(const float4*)(Apn + 64 * KDIM);
            br0 = *(const float4*)Wpn;
            br1 = *(const float4*)(Wpn + 64 * KDIM);
        }
#pragma unroll
        for (int k = 0; k < 16; k++) {
            float4 a0 = *(const float4*)(&As[k][ty * 4]);
            float4 a1 = *(const float4*)(&As[k][64 + ty * 4]);
            ulonglong2 b0 = *(const ulonglong2*)(&Bs[k][tx * 4]);
            ulonglong2 b1 = *(const ulonglong2*)(&Bs[k][64 + tx * 4]);
            ull ad[8];
            ad[0] = dup2(a0.x); ad[1] = dup2(a0.y); ad[2] = dup2(a0.z); ad[3] = dup2(a0.w);
            ad[4] = dup2(a1.x); ad[5] = dup2(a1.y); ad[6] = dup2(a1.z); ad[7] = dup2(a1.w);
#pragma unroll
            for (int i = 0; i < 8; i++) {
                ffma2(acc[i][0], ad[i], b0.x);
                ffma2(acc[i][1], ad[i], b0.y);
                ffma2(acc[i][2], ad[i], b1.x);
                ffma2(acc[i][3], ad[i], b1.y);
            }
        }
    }

    float4 bs0 = *(const float4*)(bias + colBase + tx * 4);
    float4 bs1 = *(const float4*)(bias + colBase + 64 + tx * 4);
#pragma unroll
    for (int i = 0; i < 8; i++) {
        int row = rowBase + (i < 4 ? ty * 4 + i : 64 + ty * 4 + (i - 4));
        float2 p0 = unpk(acc[i][0]);
        float2 p1 = unpk(acc[i][1]);
        float2 p2 = unpk(acc[i][2]);
        float2 p3 = unpk(acc[i][3]);
        float4 v0 = make_float4(p0.x + bs0.x, p0.y + bs0.y, p1.x + bs0.z, p1.y + bs0.w);
        float4 v1 = make_float4(p2.x + bs1.x, p2.y + bs1.y, p3.x + bs1.z, p3.y + bs1.w);
        *(float4*)(C + (size_t)row * N + colBase + tx * 4)      = v0;
        *(float4*)(C + (size_t)row * N + colBase + 64 + tx * 4) = v1;
    }
}

// ---------------- persistent encoder layer (HC=256, 2 dirs) ----------------
// grid = GRID_P blocks x 256 threads. Block owns 4 consecutive global units
// (unit index = dir*256 + u). Thread: ul = tid&3 (unit), b = tid>>2 (batch).
// Weights stay in SMEM all 40 steps; c in registers; h via global ping-pong.
__global__ __launch_bounds__(256) void enc_seq_kernel(
    const float* __restrict__ xgA, const float* __restrict__ xgB,
    const float* __restrict__ Whh, const float* __restrict__ bhh,
    float* __restrict__ hbuf, float* __restrict__ y,
    float* __restrict__ hf, float* __restrict__ cf) {
    const int HC = 256, LD = HC + 4;          // padded row stride (65 x 16B, conflict-free)
    extern __shared__ float sm[];
    float* w_sh = sm;                         // [16][LD]
    float* h_sh = sm + 16 * LD;               // [64][LD]

    const int tid = threadIdx.x;
    const int ul = tid & 3;
    const int b  = tid >> 2;
    const int gunit = blockIdx.x * 4;         // 0..508
    const int dir = gunit >> 8;
    const int ub  = gunit & 255;              // unit base within dir
    const int u   = ub + ul;

    const float* Wd  = Whh + (size_t)dir * 4 * HC * HC;
    const float* bb  = bhh + dir * 4 * HC;
    const float* xgd = dir ? xgB : xgA;

    // preload this block's 16 weight rows (4 gates x 4 units) into smem
    for (int i = tid; i < 16 * (HC / 4); i += 256) {
        int r = i / (HC / 4), k4 = i % (HC / 4);
        int g = r >> 2, j = r & 3;
        float4 v = __ldg((const float4*)(Wd + (size_t)(g * HC + ub + j) * HC + k4 * 4));
        *(float4*)&w_sh[r * LD + k4 * 4] = v;
    }

    // init state: h0 = 0, c0 = 0
    float c_reg = 0.f, hn = 0.f;
    hbuf[dir * B_ * HC + b * HC + u] = 0.f;   // buffer 0
    const float bi = bb[0 * HC + u], bfg = bb[1 * HC + u];
    const float bg = bb[2 * HC + u], bo  = bb[3 * HC + u];
    grid_bar();

    const float* w0 = &w_sh[(0 * 4 + ul) * LD];
    const float* w1 = &w_sh[(1 * 4 + ul) * LD];
    const float* w2 = &w_sh[(2 * 4 + ul) * LD];
    const float* w3 = &w_sh[(3 * 4 + ul) * LD];
    const float* hr = &h_sh[b * LD];

    for (int s = 0; s < T_; s++) {
        const float* hin = hbuf + (size_t)(s & 1) * (B_ * 512) + dir * B_ * HC;
        for (int i = tid; i < B_ * (HC / 4); i += 256) {
            int r = i / (HC / 4), k4 = i % (HC / 4);
            float4 v = __ldcg((const float4*)(hin + (size_t)r * HC + k4 * 4));
            *(float4*)&h_sh[r * LD + k4 * 4] = v;
        }
        __syncthreads();

        float a0 = 0.f, a1 = 0.f, a2 = 0.f, a3 = 0.f;
#pragma unroll 8
        for (int k = 0; k < HC; k += 4) {
            float4 hv = *(const float4*)(hr + k);
            float4 v0 = *(const float4*)(w0 + k);
            float4 v1 = *(const float4*)(w1 + k);
            float4 v2 = *(const float4*)(w2 + k);
            float4 v3 = *(const float4*)(w3 + k);
            a0 += hv.x * v0.x + hv.y * v0.y + hv.z * v0.z + hv.w * v0.w;
            a1 += hv.x * v1.x + hv.y * v1.y + hv.z * v1.z + hv.w * v1.w;
            a2 += hv.x * v2.x + hv.y * v2.y + hv.z * v2.z + hv.w * v2.w;
            a3 += hv.x * v3.x + hv.y * v3.y + hv.z * v3.z + hv.w * v3.w;
        }
        const int t = dir ? (T_ - 1 - s) : s;
        const float* xr = xgd + ((size_t)t * B_ + b) * 4 * HC;
        float gi = xr[0 * HC + u] + a0 + bi;
        float gf = xr[1 * HC + u] + a1 + bfg;
        float gg = xr[2 * HC + u] + a2 + bg;
        float go = xr[3 * HC + u] + a3 + bo;
        float ii = 1.f / (1.f + expf(-gi));
        float ff = 1.f / (1.f + expf(-gf));
        float oo = 1.f / (1.f + expf(-go));
        c_reg = ff * c_reg + ii * tanhf(gg);
        hn = oo * tanhf(c_reg);
        hbuf[(size_t)((s + 1) & 1) * (B_ * 512) + dir * B_ * HC + b * HC + u] = hn;
        y[((size_t)t * B_ + b) * 512 + dir * HC + u] = hn;
        if (s + 1 < T_) grid_bar();
    }
    hf[b * 512 + dir * HC + u] = hn;
    cf[b * 512 + dir * HC + u] = c_reg;
}

// ---------------- persistent decoder layer (HC=512) ----------------
__global__ __launch_bounds__(256) void dec_seq_kernel(
    const float* __restrict__ xg,
    const float* __restrict__ Whh, const float* __restrict__ bhh,
    const float* __restrict__ hf, const float* __restrict__ cf,
    float* __restrict__ hbuf, float* __restrict__ y) {
    const int HC = 512, LD = HC + 4;
    extern __shared__ float sm[];
    float* w_sh = sm;                         // [16][LD]
    float* h_sh = sm + 16 * LD;               // [64][LD]

    const int tid = threadIdx.x;
    const int ul = tid & 3;
    const int b  = tid >> 2;
    const int ub = blockIdx.x * 4;            // 0..508
    const int u  = ub + ul;

    for (int i = tid; i < 16 * (HC / 4); i += 256) {
        int r = i / (HC / 4), k4 = i % (HC / 4);
        int g = r >> 2, j = r & 3;
        float4 v = __ldg((const float4*)(Whh + (size_t)(g * HC + ub + j) * HC + k4 * 4));
        *(float4*)&w_sh[r * LD + k4 * 4] = v;
    }

    float c_reg = cf[b * 512 + u];
    hbuf[b * HC + u] = hf[b * 512 + u];       // buffer 0
    const float bi = bhh[0 * HC + u], bfg = bhh[1 * HC + u];
    const float bg = bhh[2 * HC + u], bo  = bhh[3 * HC + u];
    grid_bar();

    const float* w0 = &w_sh[(0 * 4 + ul) * LD];
    const float* w1 = &w_sh[(1 * 4 + ul) * LD];
    const float* w2 = &w_sh[(2 * 4 + ul) * LD];
    const float* w3 = &w_sh[(3 * 4 + ul) * LD];
    const float* hr = &h_sh[b * LD];

    for (int s = 0; s < T_; s++) {
        const float* hin = hbuf + (size_t)(s & 1) * (B_ * 512);
        for (int i = tid; i < B_ * (HC / 4); i += 256) {
            int r = i / (HC / 4), k4 = i % (HC / 4);
            float4 v = __ldcg((const float4*)(hin + (size_t)r * HC + k4 * 4));
            *(float4*)&h_sh[r * LD + k4 * 4] = v;
        }
        __syncthreads();

        float a0 = 0.f, a1 = 0.f, a2 = 0.f, a3 = 0.f;
#pragma unroll 8
        for (int k = 0; k < HC; k += 4) {
            float4 hv = *(const float4*)(hr + k);
            float4 v0 = *(const float4*)(w0 + k);
            float4 v1 = *(const float4*)(w1 + k);
            float4 v2 = *(const float4*)(w2 + k);
            float4 v3 = *(const float4*)(w3 + k);
            a0 += hv.x * v0.x + hv.y * v0.y + hv.z * v0.z + hv.w * v0.w;
            a1 += hv.x * v1.x + hv.y * v1.y + hv.z * v1.z + hv.w * v1.w;
            a2 += hv.x * v2.x + hv.y * v2.y + hv.z * v2.z + hv.w * v2.w;
            a3 += hv.x * v3.x + hv.y * v3.y + hv.z * v3.z + hv.w * v3.w;
        }
        const float* xr = xg + ((size_t)s * B_ + b) * 4 * HC;
        float gi = xr[0 * HC + u] + a0 + bi;
        float gf = xr[1 * HC + u] + a1 + bfg;
        float gg = xr[2 * HC + u] + a2 + bg;
        float go = xr[3 * HC + u] + a3 + bo;
        float ii = 1.f / (1.f + expf(-gi));
        float ff = 1.f / (1.f + expf(-gf));
        float oo = 1.f / (1.f + expf(-go));
        c_reg = ff * c_reg + ii * tanhf(gg);
        float hn = oo * tanhf(c_reg);
        hbuf[(size_t)((s + 1) & 1) * (B_ * 512) + b * HC + u] = hn;
        y[((size_t)s * B_ + b) * 512 + u] = hn;
        if (s + 1 < T_) grid_bar();
    }
}

static inline void launch_gemm(const float* A, const float* W, const float* bias,
                               float* C, int M, int N) {
    dim3 g(N / 128, M / 128), bl(256);
    gemm_bias_kernel<<<g, bl>>>(A, W, bias, C, M, N);
}

extern "C" void kernel_launch(void* const* d_in, const int* in_sizes, int n_in,
                              void* d_out, int out_size) {
    (void)in_sizes; (void)n_in; (void)out_size;
    const int*   src      = (const int*)  d_in[0];
    const int*   tgt      = (const int*)  d_in[1];
    const float* src_emb  = (const float*)d_in[2];
    const float* tgt_emb  = (const float*)d_in[3];
    const float* enc_Wih  = (const float*)d_in[4];   // [2,2,1024,512]
    const float* enc_Whh  = (const float*)d_in[5];   // [2,2,1024,256]
    const float* enc_bih  = (const float*)d_in[6];   // [2,2,1024]
    const float* enc_bhh  = (const float*)d_in[7];   // [2,2,1024]
    const float* dec_Wih  = (const float*)d_in[8];   // [2,2048,512]
    const float* dec_Whh  = (const float*)d_in[9];   // [2,2048,512]
    const float* dec_bih  = (const float*)d_in[10];  // [2,2048]
    const float* dec_bhh  = (const float*)d_in[11];  // [2,2048]
    const float* lin_W    = (const float*)d_in[12];  // [32000,512]
    const float* lin_b    = (const float*)d_in[13];  // [32000]
    float* logits = (float*)d_out;

    float *xA, *xB, *hbuf, *hfA, *cfA, *xgA, *xgB, *xgD;
    cudaGetSymbolAddress((void**)&xA,   g_x);
    cudaGetSymbolAddress((void**)&xB,   g_y);
    cudaGetSymbolAddress((void**)&hbuf, g_hbuf);
    cudaGetSymbolAddress((void**)&hfA,  g_hf);
    cudaGetSymbolAddress((void**)&cfA,  g_cf);
    cudaGetSymbolAddress((void**)&xgA,  g_xgA);
    cudaGetSymbolAddress((void**)&xgB,  g_xgB);
    cudaGetSymbolAddress((void**)&xgD,  g_xgD);

    const int SMEM_ENC = (16 + 64) * (256 + 4) * sizeof(float);  // 83,200 B
    const int SMEM_DEC = (16 + 64) * (512 + 4) * sizeof(float);  // 165,120 B
    cudaFuncSetAttribute(enc_seq_kernel, cudaFuncAttributeMaxDynamicSharedMemorySize, SMEM_ENC);
    cudaFuncSetAttribute(dec_seq_kernel, cudaFuncAttributeMaxDynamicSharedMemorySize, SMEM_DEC);

    // ---- source embedding ----
    embed_kernel<<<TB_, 128>>>(src, src_emb, xA);

    // ---- encoder: 2 stacked bidirectional layers ----
    float* ein = xA;
    float* eout = xB;
    for (int l = 0; l < 2; l++) {
        const float* Wih = enc_Wih + (size_t)l * 2 * 1024 * 512;
        const float* Whh = enc_Whh + (size_t)l * 2 * 1024 * 256;
        const float* bih = enc_bih + (size_t)l * 2 * 1024;
        const float* bhh = enc_bhh + (size_t)l * 2 * 1024;
        launch_gemm(ein, Wih,              bih,        xgA, TB_, 1024);
        launch_gemm(ein, Wih + 1024 * 512, bih + 1024, xgB, TB_, 1024);
        enc_seq_kernel<<<GRID_P, 256, SMEM_ENC>>>(
            xgA, xgB, Whh, bhh, hbuf, eout,
            hfA + (size_t)l * B_ * 512, cfA + (size_t)l * B_ * 512);
        float* tmp = ein; ein = eout; eout = tmp;
    }

    // ---- target embedding (reuse the now-free buffer) ----
    float* din = eout;
    float* dout = ein;
    embed_kernel<<<TB_, 128>>>(tgt, tgt_emb, din);

    // ---- decoder: 2 stacked layers, hidden 512 ----
    for (int l = 0; l < 2; l++) {
        const float* Wih = dec_Wih + (size_t)l * 2048 * 512;
        const float* Whh = dec_Whh + (size_t)l * 2048 * 512;
        const float* bih = dec_bih + (size_t)l * 2048;
        const float* bhh = dec_bhh + (size_t)l * 2048;
        launch_gemm(din, Wih, bih, xgD, TB_, 2048);
        dec_seq_kernel<<<GRID_P, 256, SMEM_DEC>>>(
            xgD, Whh, bhh,
            hfA + (size_t)l * B_ * 512, cfA + (size_t)l * B_ * 512,
            hbuf, dout);
        float* tmp = din; din = dout; dout = tmp;
    }

    // ---- final projection: logits[2560,32000] = y @ lin_W^T + lin_b ----
    launch_gemm(din, lin_W, lin_b, logits, TB_, 32000);
}

// round 15
// speedup vs baseline: 1.1749x; 1.0017x over previous
#include <cuda_runtime.h>
#include <math.h>

#define T_   40
#define B_   64
#define TB_  2560      // T*B
#define KDIM 512       // all GEMM K dims are 512 (E == 2H)
#define GRID_P 128     // persistent grid size (<= SM count; all co-resident)

typedef unsigned long long ull;

// ---------------- packed f32x2 helpers (sm_100+) ----------------
__device__ __forceinline__ void ffma2(ull &d, ull a, ull b) {
    asm("fma.rn.f32x2 %0, %1, %2, %0;" : "+l"(d) : "l"(a), "l"(b));
}
__device__ __forceinline__ ull dup2(float x) {
    ull r; asm("mov.b64 %0, {%1, %1};" : "=l"(r) : "f"(x)); return r;
}
__device__ __forceinline__ float2 unpk(ull v) {
    float2 r; asm("mov.b64 {%0, %1}, %2;" : "=f"(r.x), "=f"(r.y) : "l"(v)); return r;
}

// ---------------- device scratch (no allocations allowed) ----------------
__device__ float g_x[TB_ * 512];
__device__ float g_y[TB_ * 512];
__device__ float g_xgA[TB_ * 1024];       // encoder fwd xg
__device__ float g_xgB[TB_ * 1024];       // encoder bwd xg
__device__ float g_xgD[TB_ * 2048];       // decoder xg
__device__ float g_hbuf[2][B_ * 512];     // ping-pong h (enc: [dir][b][256]; dec: [b][512])
__device__ float g_hf[2][B_ * 512];       // encoder finals per layer (concat fwd,bwd)
__device__ float g_cf[2][B_ * 512];
__device__ unsigned g_bar_cnt;            // grid barrier state (zero-init)
__device__ unsigned g_bar_gen;

// ---------------- grid-wide barrier (all GRID_P blocks co-resident) ------
__device__ __forceinline__ void grid_bar() {
    __threadfence();
    __syncthreads();
    if (threadIdx.x == 0) {
        unsigned gen = *((volatile unsigned*)&g_bar_gen);
        unsigned t = atomicAdd(&g_bar_cnt, 1u);
        if (t == GRID_P - 1) {
            g_bar_cnt = 0;
            __threadfence();
            *((volatile unsigned*)&g_bar_gen) = gen + 1;
        } else {
            while (*((volatile unsigned*)&g_bar_gen) == gen) { __nanosleep(32); }
        }
    }
    __syncthreads();
}

// ---------------- embedding gather ----------------
__global__ void embed_kernel(const int* __restrict__ tok,
                             const float* __restrict__ emb,
                             float* __restrict__ out) {
    int row = blockIdx.x;                 // 0..TB_-1
    int t = tok[row];
    const float4* s = reinterpret_cast<const float4*>(emb + (size_t)t * 512);
    float4* d = reinterpret_cast<float4*>(out + (size_t)row * 512);
    d[threadIdx.x] = s[threadIdx.x];      // 128 threads * float4 = 512 floats
}

// ---------------- fp32 GEMM with packed f32x2 FMA ----------------
// C[M,N] = A[M,512] * W[N,512]^T + bias[N]
__global__ __launch_bounds__(256) void gemm_bias_kernel(
    const float* __restrict__ A, const float* __restrict__ W,
    const float* __restrict__ bias, float* __restrict__ C,
    int M, int N) {
    __shared__ __align__(16) float As[16][128];
    __shared__ __align__(16) float Bs[16][128];

    const int tid = threadIdx.x;
    const int tx = tid & 15;
    const int ty = tid >> 4;
    const int rowBase = blockIdx.y * 128;
    const int colBase = blockIdx.x * 128;
    const int lrow = tid >> 2;            // 0..63
    const int lk = (tid & 3) * 4;         // 0,4,8,12

    const float* Ap = A + (size_t)(rowBase + lrow) * KDIM + lk;
    const float* Wp = W + (size_t)(colBase + lrow) * KDIM + lk;

    float4 ar0 = *(const float4*)Ap;
    float4 ar1 = *(const float4*)(Ap + 64 * KDIM);
    float4 br0 = *(const float4*)Wp;
    float4 br1 = *(const float4*)(Wp + 64 * KDIM);

    ull acc[8][4];
#pragma unroll
    for (int i = 0; i < 8; i++)
#pragma unroll
        for (int j = 0; j < 4; j++) acc[i][j] = 0ull;

    const int NKB = KDIM / 16;
    for (int kb = 0; kb < NKB; kb++) {
        __syncthreads();
        As[lk + 0][lrow]      = ar0.x; As[lk + 1][lrow]      = ar0.y;
        As[lk + 2][lrow]      = ar0.z; As[lk + 3][lrow]      = ar0.w;
        As[lk + 0][lrow + 64] = ar1.x; As[lk + 1][lrow + 64] = ar1.y;
        As[lk + 2][lrow + 64] = ar1.z; As[lk + 3][lrow + 64] = ar1.w;
        Bs[lk + 0][lrow]      = br0.x; Bs[lk + 1][lrow]      = br0.y;
        Bs[lk + 2][lrow]      = br0.z; Bs[lk + 3][lrow]      = br0.w;
        Bs[lk + 0][lrow + 64] = br1.x; Bs[lk + 1][lrow + 64] = br1.y;
        Bs[lk + 2][lrow + 64] = br1.z; Bs[lk + 3][lrow + 64] = br1.w;
        __syncthreads();
        if (kb + 1 < NKB) {
            const float* Apn = Ap + (kb + 1) * 16;
            const float* Wpn = Wp + (kb + 1) * 16;
            ar0 = *(const float4*)Apn;
            ar1 = *(const float4*)(Apn + 64 * KDIM);
            br0 = *(const float4*)Wpn;
            br1 = *(const float4*)(Wpn + 64 * KDIM);
        }
#pragma unroll
        for (int k = 0; k < 16; k++) {
            float4 a0 = *(const float4*)(&As[k][ty * 4]);
            float4 a1 = *(const float4*)(&As[k][64 + ty * 4]);
            ulonglong2 b0 = *(const ulonglong2*)(&Bs[k][tx * 4]);
            ulonglong2 b1 = *(const ulonglong2*)(&Bs[k][64 + tx * 4]);
            ull ad[8];
            ad[0] = dup2(a0.x); ad[1] = dup2(a0.y); ad[2] = dup2(a0.z); ad[3] = dup2(a0.w);
            ad[4] = dup2(a1.x); ad[5] = dup2(a1.y); ad[6] = dup2(a1.z); ad[7] = dup2(a1.w);
#pragma unroll
            for (int i = 0; i < 8; i++) {
                ffma2(acc[i][0], ad[i], b0.x);
                ffma2(acc[i][1], ad[i], b0.y);
                ffma2(acc[i][2], ad[i], b1.x);
                ffma2(acc[i][3], ad[i], b1.y);
            }
        }
    }

    float4 bs0 = *(const float4*)(bias + colBase + tx * 4);
    float4 bs1 = *(const float4*)(bias + colBase + 64 + tx * 4);
#pragma unroll
    for (int i = 0; i < 8; i++) {
        int row = rowBase + (i < 4 ? ty * 4 + i : 64 + ty * 4 + (i - 4));
        float2 p0 = unpk(acc[i][0]);
        float2 p1 = unpk(acc[i][1]);
        float2 p2 = unpk(acc[i][2]);
        float2 p3 = unpk(acc[i][3]);
        float4 v0 = make_float4(p0.x + bs0.x, p0.y + bs0.y, p1.x + bs0.z, p1.y + bs0.w);
        float4 v1 = make_float4(p2.x + bs1.x, p2.y + bs1.y, p3.x + bs1.z, p3.y + bs1.w);
        *(float4*)(C + (size_t)row * N + colBase + tx * 4)      = v0;
        *(float4*)(C + (size_t)row * N + colBase + 64 + tx * 4) = v1;
    }
}

// ---------------- persistent encoder layer (HC=256, 2 dirs) ----------------
// grid = GRID_P blocks x 256 threads. Block owns 4 consecutive global units
// (unit index = dir*256 + u). Thread: ul = tid&3 (unit), b = tid>>2 (batch).
// Weights stay in SMEM all 40 steps; c in registers; h via global ping-pong.
__global__ __launch_bounds__(256) void enc_seq_kernel(
    const float* __restrict__ xgA, const float* __restrict__ xgB,
    const float* __restrict__ Whh, const float* __restrict__ bhh,
    float* __restrict__ hbuf, float* __restrict__ y,
    float* __restrict__ hf, float* __restrict__ cf) {
    const int HC = 256, LD = HC + 4;          // padded row stride (65 x 16B, conflict-free)
    extern __shared__ float sm[];
    float* w_sh = sm;                         // [16][LD]
    float* h_sh = sm + 16 * LD;               // [64][LD]

    const int tid = threadIdx.x;
    const int ul = tid & 3;
    const int b  = tid >> 2;
    const int gunit = blockIdx.x * 4;         // 0..508
    const int dir = gunit >> 8;
    const int ub  = gunit & 255;              // unit base within dir
    const int u   = ub + ul;

    const float* Wd  = Whh + (size_t)dir * 4 * HC * HC;
    const float* bb  = bhh + dir * 4 * HC;
    const float* xgd = dir ? xgB : xgA;

    // preload this block's 16 weight rows (4 gates x 4 units) into smem
    for (int i = tid; i < 16 * (HC / 4); i += 256) {
        int r = i / (HC / 4), k4 = i % (HC / 4);
        int g = r >> 2, j = r & 3;
        float4 v = __ldg((const float4*)(Wd + (size_t)(g * HC + ub + j) * HC + k4 * 4));
        *(float4*)&w_sh[r * LD + k4 * 4] = v;
    }

    // init state: h0 = 0, c0 = 0
    float c_reg = 0.f, hn = 0.f;
    hbuf[dir * B_ * HC + b * HC + u] = 0.f;   // buffer 0
    const float bi = bb[0 * HC + u], bfg = bb[1 * HC + u];
    const float bg = bb[2 * HC + u], bo  = bb[3 * HC + u];
    grid_bar();

    const float* w0 = &w_sh[(0 * 4 + ul) * LD];
    const float* w1 = &w_sh[(1 * 4 + ul) * LD];
    const float* w2 = &w_sh[(2 * 4 + ul) * LD];
    const float* w3 = &w_sh[(3 * 4 + ul) * LD];
    const float* hr = &h_sh[b * LD];

    for (int s = 0; s < T_; s++) {
        const float* hin = hbuf + (size_t)(s & 1) * (B_ * 512) + dir * B_ * HC;
        for (int i = tid; i < B_ * (HC / 4); i += 256) {
            int r = i / (HC / 4), k4 = i % (HC / 4);
            float4 v = __ldcg((const float4*)(hin + (size_t)r * HC + k4 * 4));
            *(float4*)&h_sh[r * LD + k4 * 4] = v;
        }
        __syncthreads();

        float a0 = 0.f, a1 = 0.f, a2 = 0.f, a3 = 0.f;
#pragma unroll 8
        for (int k = 0; k < HC; k += 4) {
            float4 hv = *(const float4*)(hr + k);
            float4 v0 = *(const float4*)(w0 + k);
            float4 v1 = *(const float4*)(w1 + k);
            float4 v2 = *(const float4*)(w2 + k);
            float4 v3 = *(const float4*)(w3 + k);
            a0 += hv.x * v0.x + hv.y * v0.y + hv.z * v0.z + hv.w * v0.w;
            a1 += hv.x * v1.x + hv.y * v1.y + hv.z * v1.z + hv.w * v1.w;
            a2 += hv.x * v2.x + hv.y * v2.y + hv.z * v2.z + hv.w * v2.w;
            a3 += hv.x * v3.x + hv.y * v3.y + hv.z * v3.z + hv.w * v3.w;
        }
        const int t = dir ? (T_ - 1 - s) : s;
        const float* xr = xgd + ((size_t)t * B_ + b) * 4 * HC;
        float gi = xr[0 * HC + u] + a0 + bi;
        float gf = xr[1 * HC + u] + a1 + bfg;
        float gg = xr[2 * HC + u] + a2 + bg;
        float go = xr[3 * HC + u] + a3 + bo;
        float ii = 1.f / (1.f + expf(-gi));
        float ff = 1.f / (1.f + expf(-gf));
        float oo = 1.f / (1.f + expf(-go));
        c_reg = ff * c_reg + ii * tanhf(gg);
        hn = oo * tanhf(c_reg);
        hbuf[(size_t)((s + 1) & 1) * (B_ * 512) + dir * B_ * HC + b * HC + u] = hn;
        y[((size_t)t * B_ + b) * 512 + dir * HC + u] = hn;
        if (s + 1 < T_) grid_bar();
    }
    hf[b * 512 + dir * HC + u] = hn;
    cf[b * 512 + dir * HC + u] = c_reg;
}

// ---------------- persistent decoder layer (HC=512) ----------------
__global__ __launch_bounds__(256) void dec_seq_kernel(
    const float* __restrict__ xg,
    const float* __restrict__ Whh, const float* __restrict__ bhh,
    const float* __restrict__ hf, const float* __restrict__ cf,
    float* __restrict__ hbuf, float* __restrict__ y) {
    const int HC = 512, LD = HC + 4;
    extern __shared__ float sm[];
    float* w_sh = sm;                         // [16][LD]
    float* h_sh = sm + 16 * LD;               // [64][LD]

    const int tid = threadIdx.x;
    const int ul = tid & 3;
    const int b  = tid >> 2;
    const int ub = blockIdx.x * 4;            // 0..508
    const int u  = ub + ul;

    for (int i = tid; i < 16 * (HC / 4); i += 256) {
        int r = i / (HC / 4), k4 = i % (HC / 4);
        int g = r >> 2, j = r & 3;
        float4 v = __ldg((const float4*)(Whh + (size_t)(g * HC + ub + j) * HC + k4 * 4));
        *(float4*)&w_sh[r * LD + k4 * 4] = v;
    }

    float c_reg = cf[b * 512 + u];
    hbuf[b * HC + u] = hf[b * 512 + u];       // buffer 0
    const float bi = bhh[0 * HC + u], bfg = bhh[1 * HC + u];
    const float bg = bhh[2 * HC + u], bo  = bhh[3 * HC + u];
    grid_bar();

    const float* w0 = &w_sh[(0 * 4 + ul) * LD];
    const float* w1 = &w_sh[(1 * 4 + ul) * LD];
    const float* w2 = &w_sh[(2 * 4 + ul) * LD];
    const float* w3 = &w_sh[(3 * 4 + ul) * LD];
    const float* hr = &h_sh[b * LD];

    for (int s = 0; s < T_; s++) {
        const float* hin = hbuf + (size_t)(s & 1) * (B_ * 512);
        for (int i = tid; i < B_ * (HC / 4); i += 256) {
            int r = i / (HC / 4), k4 = i % (HC / 4);
            float4 v = __ldcg((const float4*)(hin + (size_t)r * HC + k4 * 4));
            *(float4*)&h_sh[r * LD + k4 * 4] = v;
        }
        __syncthreads();

        float a0 = 0.f, a1 = 0.f, a2 = 0.f, a3 = 0.f;
#pragma unroll 8
        for (int k = 0; k < HC; k += 4) {
            float4 hv = *(const float4*)(hr + k);
            float4 v0 = *(const float4*)(w0 + k);
            float4 v1 = *(const float4*)(w1 + k);
            float4 v2 = *(const float4*)(w2 + k);
            float4 v3 = *(const float4*)(w3 + k);
            a0 += hv.x * v0.x + hv.y * v0.y + hv.z * v0.z + hv.w * v0.w;
            a1 += hv.x * v1.x + hv.y * v1.y + hv.z * v1.z + hv.w * v1.w;
            a2 += hv.x * v2.x + hv.y * v2.y + hv.z * v2.z + hv.w * v2.w;
            a3 += hv.x * v3.x + hv.y * v3.y + hv.z * v3.z + hv.w * v3.w;
        }
        const float* xr = xg + ((size_t)s * B_ + b) * 4 * HC;
        float gi = xr[0 * HC + u] + a0 + bi;
        float gf = xr[1 * HC + u] + a1 + bfg;
        float gg = xr[2 * HC + u] + a2 + bg;
        float go = xr[3 * HC + u] + a3 + bo;
        float ii = 1.f / (1.f + expf(-gi));
        float ff = 1.f / (1.f + expf(-gf));
        float oo = 1.f / (1.f + expf(-go));
        c_reg = ff * c_reg + ii * tanhf(gg);
        float hn = oo * tanhf(c_reg);
        hbuf[(size_t)((s + 1) & 1) * (B_ * 512) + b * HC + u] = hn;
        y[((size_t)s * B_ + b) * 512 + u] = hn;
        if (s + 1 < T_) grid_bar();
    }
}

static inline void launch_gemm(const float* A, const float* W, const float* bias,
                               float* C, int M, int N) {
    dim3 g(N / 128, M / 128), bl(256);
    gemm_bias_kernel<<<g, bl>>>(A, W, bias, C, M, N);
}

extern "C" void kernel_launch(void* const* d_in, const int* in_sizes, int n_in,
                              void* d_out, int out_size) {
    (void)in_sizes; (void)n_in; (void)out_size;
    const int*   src      = (const int*)  d_in[0];
    const int*   tgt      = (const int*)  d_in[1];
    const float* src_emb  = (const float*)d_in[2];
    const float* tgt_emb  = (const float*)d_in[3];
    const float* enc_Wih  = (const float*)d_in[4];   // [2,2,1024,512]
    const float* enc_Whh  = (const float*)d_in[5];   // [2,2,1024,256]
    const float* enc_bih  = (const float*)d_in[6];   // [2,2,1024]
    const float* enc_bhh  = (const float*)d_in[7];   // [2,2,1024]
    const float* dec_Wih  = (const float*)d_in[8];   // [2,2048,512]
    const float* dec_Whh  = (const float*)d_in[9];   // [2,2048,512]
    const float* dec_bih  = (const float*)d_in[10];  // [2,2048]
    const float* dec_bhh  = (const float*)d_in[11];  // [2,2048]
    const float* lin_W    = (const float*)d_in[12];  // [32000,512]
    const float* lin_b    = (const float*)d_in[13];  // [32000]
    float* logits = (float*)d_out;

    float *xA, *xB, *hbuf, *hfA, *cfA, *xgA, *xgB, *xgD;
    cudaGetSymbolAddress((void**)&xA,   g_x);
    cudaGetSymbolAddress((void**)&xB,   g_y);
    cudaGetSymbolAddress((void**)&hbuf, g_hbuf);
    cudaGetSymbolAddress((void**)&hfA,  g_hf);
    cudaGetSymbolAddress((void**)&cfA,  g_cf);
    cudaGetSymbolAddress((void**)&xgA,  g_xgA);
    cudaGetSymbolAddress((void**)&xgB,  g_xgB);
    cudaGetSymbolAddress((void**)&xgD,  g_xgD);

    const int SMEM_ENC = (16 + 64) * (256 + 4) * sizeof(float);  // 83,200 B
    const int SMEM_DEC = (16 + 64) * (512 + 4) * sizeof(float);  // 165,120 B
    cudaFuncSetAttribute(enc_seq_kernel, cudaFuncAttributeMaxDynamicSharedMemorySize, SMEM_ENC);
    cudaFuncSetAttribute(dec_seq_kernel, cudaFuncAttributeMaxDynamicSharedMemorySize, SMEM_DEC);

    // ---- source embedding ----
    embed_kernel<<<TB_, 128>>>(src, src_emb, xA);

    // ---- encoder: 2 stacked bidirectional layers ----
    float* ein = xA;
    float* eout = xB;
    for (int l = 0; l < 2; l++) {
        const float* Wih = enc_Wih + (size_t)l * 2 * 1024 * 512;
        const float* Whh = enc_Whh + (size_t)l * 2 * 1024 * 256;
        const float* bih = enc_bih + (size_t)l * 2 * 1024;
        const float* bhh = enc_bhh + (size_t)l * 2 * 1024;
        launch_gemm(ein, Wih,              bih,        xgA, TB_, 1024);
        launch_gemm(ein, Wih + 1024 * 512, bih + 1024, xgB, TB_, 1024);
        enc_seq_kernel<<<GRID_P, 256, SMEM_ENC>>>(
            xgA, xgB, Whh, bhh, hbuf, eout,
            hfA + (size_t)l * B_ * 512, cfA + (size_t)l * B_ * 512);
        float* tmp = ein; ein = eout; eout = tmp;
    }

    // ---- target embedding (reuse the now-free buffer) ----
    float* din = eout;
    float* dout = ein;
    embed_kernel<<<TB_, 128>>>(tgt, tgt_emb, din);

    // ---- decoder: 2 stacked layers, hidden 512 ----
    for (int l = 0; l < 2; l++) {
        const float* Wih = dec_Wih + (size_t)l * 2048 * 512;
        const float* Whh = dec_Whh + (size_t)l * 2048 * 512;
        const float* bih = dec_bih + (size_t)l * 2048;
        const float* bhh = dec_bhh + (size_t)l * 2048;
        launch_gemm(din, Wih, bih, xgD, TB_, 2048);
        dec_seq_kernel<<<GRID_P, 256, SMEM_DEC>>>(
            xgD, Whh, bhh,
            hfA + (size_t)l * B_ * 512, cfA + (size_t)l * B_ * 512,
            hbuf, dout);
        float* tmp = din; din = dout; dout = tmp;
    }

    // ---- final projection: logits[2560,32000] = y @ lin_W^T + lin_b ----
    launch_gemm(din, lin_W, lin_b, logits, TB_, 32000);
}

// round 16
// speedup vs baseline: 1.4670x; 1.2486x over previous
#include <cuda_runtime.h>
#include <math.h>

#define T_   40
#define B_   64
#define TB_  2560      // T*B
#define KDIM 512       // all GEMM K dims are 512 (E == 2H)
#define GRID_P 256     // persistent grid size (2 blocks/SM, all co-resident)

typedef unsigned long long ull;

// ---------------- packed f32x2 helpers (sm_100+) ----------------
__device__ __forceinline__ void ffma2(ull &d, ull a, ull b) {
    asm("fma.rn.f32x2 %0, %1, %2, %0;" : "+l"(d) : "l"(a), "l"(b));
}
__device__ __forceinline__ ull dup2(float x) {
    ull r; asm("mov.b64 %0, {%1, %1};" : "=l"(r) : "f"(x)); return r;
}
__device__ __forceinline__ float2 unpk(ull v) {
    float2 r; asm("mov.b64 {%0, %1}, %2;" : "=f"(r.x), "=f"(r.y) : "l"(v)); return r;
}

// ---------------- device scratch (no allocations allowed) ----------------
__device__ float g_x[TB_ * 512];
__device__ float g_y[TB_ * 512];
__device__ float g_xgA[TB_ * 1024];       // encoder fwd xg
__device__ float g_xgB[TB_ * 1024];       // encoder bwd xg
__device__ float g_xgD[TB_ * 2048];       // decoder xg
__device__ float g_hbuf[2][B_ * 512];     // ping-pong h (enc: [dir][b][256]; dec: [b][512])
__device__ float g_hf[2][B_ * 512];       // encoder finals per layer (concat fwd,bwd)
__device__ float g_cf[2][B_ * 512];
__device__ unsigned g_bar_cnt;            // grid barrier state (zero-init)
__device__ unsigned g_bar_gen;

// ---------------- grid-wide barrier (all GRID_P blocks co-resident) ------
__device__ __forceinline__ void grid_bar() {
    __threadfence();
    __syncthreads();
    if (threadIdx.x == 0) {
        unsigned gen = *((volatile unsigned*)&g_bar_gen);
        unsigned t = atomicAdd(&g_bar_cnt, 1u);
        if (t == GRID_P - 1) {
            g_bar_cnt = 0;
            __threadfence();
            *((volatile unsigned*)&g_bar_gen) = gen + 1;
        } else {
            while (*((volatile unsigned*)&g_bar_gen) == gen) { __nanosleep(16); }
        }
    }
    __syncthreads();
}

// ---------------- embedding gather ----------------
__global__ void embed_kernel(const int* __restrict__ tok,
                             const float* __restrict__ emb,
                             float* __restrict__ out) {
    int row = blockIdx.x;                 // 0..TB_-1
    int t = tok[row];
    const float4* s = reinterpret_cast<const float4*>(emb + (size_t)t * 512);
    float4* d = reinterpret_cast<float4*>(out + (size_t)row * 512);
    d[threadIdx.x] = s[threadIdx.x];      // 128 threads * float4 = 512 floats
}

// ---------------- fp32 GEMM with packed f32x2 FMA ----------------
// C[M,N] = A[M,512] * W[N,512]^T + bias[N]
__global__ __launch_bounds__(256) void gemm_bias_kernel(
    const float* __restrict__ A, const float* __restrict__ W,
    const float* __restrict__ bias, float* __restrict__ C,
    int M, int N) {
    __shared__ __align__(16) float As[16][128];
    __shared__ __align__(16) float Bs[16][128];

    const int tid = threadIdx.x;
    const int tx = tid & 15;
    const int ty = tid >> 4;
    const int rowBase = blockIdx.y * 128;
    const int colBase = blockIdx.x * 128;
    const int lrow = tid >> 2;            // 0..63
    const int lk = (tid & 3) * 4;         // 0,4,8,12

    const float* Ap = A + (size_t)(rowBase + lrow) * KDIM + lk;
    const float* Wp = W + (size_t)(colBase + lrow) * KDIM + lk;

    float4 ar0 = *(const float4*)Ap;
    float4 ar1 = *(const float4*)(Ap + 64 * KDIM);
    float4 br0 = *(const float4*)Wp;
    float4 br1 = *(const float4*)(Wp + 64 * KDIM);

    ull acc[8][4];
#pragma unroll
    for (int i = 0; i < 8; i++)
#pragma unroll
        for (int j = 0; j < 4; j++) acc[i][j] = 0ull;

    const int NKB = KDIM / 16;
    for (int kb = 0; kb < NKB; kb++) {
        __syncthreads();
        As[lk + 0][lrow]      = ar0.x; As[lk + 1][lrow]      = ar0.y;
        As[lk + 2][lrow]      = ar0.z; As[lk + 3][lrow]      = ar0.w;
        As[lk + 0][lrow + 64] = ar1.x; As[lk + 1][lrow + 64] = ar1.y;
        As[lk + 2][lrow + 64] = ar1.z; As[lk + 3][lrow + 64] = ar1.w;
        Bs[lk + 0][lrow]      = br0.x; Bs[lk + 1][lrow]      = br0.y;
        Bs[lk + 2][lrow]      = br0.z; Bs[lk + 3][lrow]      = br0.w;
        Bs[lk + 0][lrow + 64] = br1.x; Bs[lk + 1][lrow + 64] = br1.y;
        Bs[lk + 2][lrow + 64] = br1.z; Bs[lk + 3][lrow + 64] = br1.w;
        __syncthreads();
        if (kb + 1 < NKB) {
            const float* Apn = Ap + (kb + 1) * 16;
            const float* Wpn = Wp + (kb + 1) * 16;
            ar0 = *(const float4*)Apn;
            ar1 = *(const float4*)(Apn + 64 * KDIM);
            br0 = *(const float4*)Wpn;
            br1 = *(const float4*)(Wpn + 64 * KDIM);
        }
#pragma unroll
        for (int k = 0; k < 16; k++) {
            float4 a0 = *(const float4*)(&As[k][ty * 4]);
            float4 a1 = *(const float4*)(&As[k][64 + ty * 4]);
            ulonglong2 b0 = *(const ulonglong2*)(&Bs[k][tx * 4]);
            ulonglong2 b1 = *(const ulonglong2*)(&Bs[k][64 + tx * 4]);
            ull ad[8];
            ad[0] = dup2(a0.x); ad[1] = dup2(a0.y); ad[2] = dup2(a0.z); ad[3] = dup2(a0.w);
            ad[4] = dup2(a1.x); ad[5] = dup2(a1.y); ad[6] = dup2(a1.z); ad[7] = dup2(a1.w);
#pragma unroll
            for (int i = 0; i < 8; i++) {
                ffma2(acc[i][0], ad[i], b0.x);
                ffma2(acc[i][1], ad[i], b0.y);
                ffma2(acc[i][2], ad[i], b1.x);
                ffma2(acc[i][3], ad[i], b1.y);
            }
        }
    }

    float4 bs0 = *(const float4*)(bias + colBase + tx * 4);
    float4 bs1 = *(const float4*)(bias + colBase + 64 + tx * 4);
#pragma unroll
    for (int i = 0; i < 8; i++) {
        int row = rowBase + (i < 4 ? ty * 4 + i : 64 + ty * 4 + (i - 4));
        float2 p0 = unpk(acc[i][0]);
        float2 p1 = unpk(acc[i][1]);
        float2 p2 = unpk(acc[i][2]);
        float2 p3 = unpk(acc[i][3]);
        float4 v0 = make_float4(p0.x + bs0.x, p0.y + bs0.y, p1.x + bs0.z, p1.y + bs0.w);
        float4 v1 = make_float4(p2.x + bs1.x, p2.y + bs1.y, p3.x + bs1.z, p3.y + bs1.w);
        *(float4*)(C + (size_t)row * N + colBase + tx * 4)      = v0;
        *(float4*)(C + (size_t)row * N + colBase + 64 + tx * 4) = v1;
    }
}

// ============================================================================
// Persistent recurrent kernels.
// 256 blocks x 256 threads, 2 blocks/SM. Block = 4 units x 32 batches (half
// of B) x 4 K-quarters. Thread: kq = tid>>6, u = (tid>>4)&3, bg = tid&15;
// owns batches (bg, bg+16) within its half. Weights for the block's 16 gate
// rows live in SMEM all T_ steps; h is broadcast per step through a global
// ping-pong and staged in SMEM transposed as [q][batch] float4 (pad 33);
// K-quarter partials reduced via SMEM; c lives in kq0 registers.
// ============================================================================

// ---------------- encoder layer (HC=256, 2 dirs in one launch) -------------
__global__ __launch_bounds__(256, 2) void enc_seq_kernel(
    const float* __restrict__ xgA, const float* __restrict__ xgB,
    const float* __restrict__ Whh, const float* __restrict__ bhh,
    float* __restrict__ hbuf, float* __restrict__ y,
    float* __restrict__ hf, float* __restrict__ cf) {
    const int HC = 256, QN = HC / 4;          // QN = 64 q-slots
    extern __shared__ float sm[];
    float* w_sh = sm;                          // 16*HC
    float* h4   = sm + 16 * HC;                // QN*33*4 floats ([q][r] float4)
    float* red  = h4 + QN * 33 * 4;            // 3*64*8

    const int tid = threadIdx.x;
    const int kq = tid >> 6;
    const int u  = (tid >> 4) & 3;
    const int bg = tid & 15;
    const int cell = tid & 63;

    const int bid = blockIdx.x;
    const int dir = bid >> 7;
    const int ublk = (bid & 127) >> 1;
    const int bhalf = bid & 1;
    const int ubase = ublk * 4;
    const int ug = ubase + u;

    const float* Wd = Whh + (size_t)dir * 4 * HC * HC;
    const float* xg = dir ? xgB : xgA;

    // weights: 16 rows (4 gates x 4 units), resident all steps
    for (int i = tid; i < 16 * QN; i += 256) {
        int r = i / QN, q = i % QN;
        int g = r >> 2, j = r & 3;
        float4 v = __ldg((const float4*)(Wd + (size_t)(g * HC + ubase + j) * HC + q * 4));
        *(float4*)&w_sh[r * HC + q * 4] = v;
    }

    float c0 = 0.f, c1 = 0.f;
    float bi0 = 0.f, bi1 = 0.f, bi2 = 0.f, bi3 = 0.f;
    if (kq == 0) {
        const float* bb = bhh + dir * 4 * HC;
        bi0 = bb[0 * HC + ug]; bi1 = bb[1 * HC + ug];
        bi2 = bb[2 * HC + ug]; bi3 = bb[3 * HC + ug];
    }
    __syncthreads();

    const float* w0 = w_sh + (0 * 4 + u) * HC + kq * (HC / 4);
    const float* w1 = w_sh + (1 * 4 + u) * HC + kq * (HC / 4);
    const float* w2 = w_sh + (2 * 4 + u) * HC + kq * (HC / 4);
    const float* w3 = w_sh + (3 * 4 + u) * HC + kq * (HC / 4);
    const float* hp0 = h4 + (size_t)(kq * (QN / 4) * 33 + bg) * 4;
    const float* hp1 = hp0 + 64;               // bg+16

    for (int s = 0; s < T_; s++) {
        const int t = dir ? (T_ - 1 - s) : s;
        float xv0[2], xv1[2], xv2[2], xv3[2];
        if (kq == 0) {
#pragma unroll
            for (int j = 0; j < 2; j++) {
                int b = bhalf * 32 + bg + j * 16;
                const float* xr = xg + ((size_t)t * B_ + b) * (4 * HC);
                xv0[j] = __ldg(xr + 0 * HC + ug);
                xv1[j] = __ldg(xr + 1 * HC + ug);
                xv2[j] = __ldg(xr + 2 * HC + ug);
                xv3[j] = __ldg(xr + 3 * HC + ug);
            }
        }
        float a00 = 0.f, a01 = 0.f, a10 = 0.f, a11 = 0.f;
        float a20 = 0.f, a21 = 0.f, a30 = 0.f, a31 = 0.f;

        if (s > 0) {
            const float* hin = hbuf + (size_t)(s & 1) * (B_ * 512)
                             + dir * (B_ * HC) + bhalf * 32 * HC;
            for (int i = tid; i < 32 * QN; i += 256) {
                int r = i >> 6, q = i & 63;    // QN = 64
                float4 v = __ldcg((const float4*)(hin + (size_t)r * HC + q * 4));
                *(float4*)&h4[(q * 33 + r) * 4] = v;
            }
            __syncthreads();
#pragma unroll 4
            for (int it = 0; it < HC / 16; it++) {
                float4 hv0 = *(const float4*)(hp0 + it * 132);
                float4 hv1 = *(const float4*)(hp1 + it * 132);
                float4 v0 = *(const float4*)(w0 + it * 4);
                float4 v1 = *(const float4*)(w1 + it * 4);
                float4 v2 = *(const float4*)(w2 + it * 4);
                float4 v3 = *(const float4*)(w3 + it * 4);
                a00 += hv0.x*v0.x + hv0.y*v0.y + hv0.z*v0.z + hv0.w*v0.w;
                a01 += hv1.x*v0.x + hv1.y*v0.y + hv1.z*v0.z + hv1.w*v0.w;
                a10 += hv0.x*v1.x + hv0.y*v1.y + hv0.z*v1.z + hv0.w*v1.w;
                a11 += hv1.x*v1.x + hv1.y*v1.y + hv1.z*v1.z + hv1.w*v1.w;
                a20 += hv0.x*v2.x + hv0.y*v2.y + hv0.z*v2.z + hv0.w*v2.w;
                a21 += hv1.x*v2.x + hv1.y*v2.y + hv1.z*v2.z + hv1.w*v2.w;
                a30 += hv0.x*v3.x + hv0.y*v3.y + hv0.z*v3.z + hv0.w*v3.w;
                a31 += hv1.x*v3.x + hv1.y*v3.y + hv1.z*v3.z + hv1.w*v3.w;
            }
            if (kq != 0) {
                float* rp = &red[((kq - 1) * 64 + cell) * 8];
                rp[0]=a00; rp[1]=a01; rp[2]=a10; rp[3]=a11;
                rp[4]=a20; rp[5]=a21; rp[6]=a30; rp[7]=a31;
            }
            __syncthreads();
            if (kq == 0) {
#pragma unroll
                for (int p = 0; p < 3; p++) {
                    const float* rp = &red[(p * 64 + cell) * 8];
                    a00+=rp[0]; a01+=rp[1]; a10+=rp[2]; a11+=rp[3];
                    a20+=rp[4]; a21+=rp[5]; a30+=rp[6]; a31+=rp[7];
                }
            }
        }

        if (kq == 0) {
#pragma unroll
            for (int j = 0; j < 2; j++) {
                float gi = xv0[j] + (j ? a01 : a00) + bi0;
                float gf = xv1[j] + (j ? a11 : a10) + bi1;
                float gg = xv2[j] + (j ? a21 : a20) + bi2;
                float go = xv3[j] + (j ? a31 : a30) + bi3;
                float ii = 1.f / (1.f + expf(-gi));
                float ff = 1.f / (1.f + expf(-gf));
                float oo = 1.f / (1.f + expf(-go));
                float cc = ff * (j ? c1 : c0) + ii * tanhf(gg);
                float hn = oo * tanhf(cc);
                if (j) c1 = cc; else c0 = cc;
                int b = bhalf * 32 + bg + j * 16;
                hbuf[(size_t)((s + 1) & 1) * (B_ * 512) + dir * (B_ * HC) + b * HC + ug] = hn;
                y[((size_t)t * B_ + b) * 512 + dir * HC + ug] = hn;
                if (s == T_ - 1) {
                    hf[b * 512 + dir * HC + ug] = hn;
                    cf[b * 512 + dir * HC + ug] = cc;
                }
            }
        }
        if (s + 1 < T_) grid_bar();
    }
}

// ---------------- decoder layer (HC=512) ----------------
__global__ __launch_bounds__(256, 2) void dec_seq_kernel(
    const float* __restrict__ xg,
    const float* __restrict__ Whh, const float* __restrict__ bhh,
    const float* __restrict__ hf, const float* __restrict__ cf,
    float* __restrict__ hbuf, float* __restrict__ y) {
    const int HC = 512, QN = HC / 4;          // QN = 128
    extern __shared__ float sm[];
    float* w_sh = sm;                          // 16*HC
    float* h4   = sm + 16 * HC;                // QN*33*4
    float* red  = h4 + QN * 33 * 4;            // 3*64*8

    const int tid = threadIdx.x;
    const int kq = tid >> 6;
    const int u  = (tid >> 4) & 3;
    const int bg = tid & 15;
    const int cell = tid & 63;

    const int bid = blockIdx.x;
    const int ublk = bid >> 1;                 // 0..127
    const int bhalf = bid & 1;
    const int ubase = ublk * 4;
    const int ug = ubase + u;

    for (int i = tid; i < 16 * QN; i += 256) {
        int r = i / QN, q = i % QN;
        int g = r >> 2, j = r & 3;
        float4 v = __ldg((const float4*)(Whh + (size_t)(g * HC + ubase + j) * HC + q * 4));
        *(float4*)&w_sh[r * HC + q * 4] = v;
    }

    float c0 = 0.f, c1 = 0.f;
    float bi0 = 0.f, bi1 = 0.f, bi2 = 0.f, bi3 = 0.f;
    if (kq == 0) {
        bi0 = bhh[0 * HC + ug]; bi1 = bhh[1 * HC + ug];
        bi2 = bhh[2 * HC + ug]; bi3 = bhh[3 * HC + ug];
        c0 = cf[(bhalf * 32 + bg) * 512 + ug];
        c1 = cf[(bhalf * 32 + bg + 16) * 512 + ug];
    }
    __syncthreads();

    const float* w0 = w_sh + (0 * 4 + u) * HC + kq * (HC / 4);
    const float* w1 = w_sh + (1 * 4 + u) * HC + kq * (HC / 4);
    const float* w2 = w_sh + (2 * 4 + u) * HC + kq * (HC / 4);
    const float* w3 = w_sh + (3 * 4 + u) * HC + kq * (HC / 4);
    const float* hp0 = h4 + (size_t)(kq * (QN / 4) * 33 + bg) * 4;
    const float* hp1 = hp0 + 64;

    for (int s = 0; s < T_; s++) {
        float xv0[2], xv1[2], xv2[2], xv3[2];
        if (kq == 0) {
#pragma unroll
            for (int j = 0; j < 2; j++) {
                int b = bhalf * 32 + bg + j * 16;
                const float* xr = xg + ((size_t)s * B_ + b) * (4 * HC);
                xv0[j] = __ldg(xr + 0 * HC + ug);
                xv1[j] = __ldg(xr + 1 * HC + ug);
                xv2[j] = __ldg(xr + 2 * HC + ug);
                xv3[j] = __ldg(xr + 3 * HC + ug);
            }
        }
        const float* hin = (s == 0)
            ? (hf + (size_t)bhalf * 32 * 512)
            : (hbuf + (size_t)(s & 1) * (B_ * 512) + (size_t)bhalf * 32 * 512);
        for (int i = tid; i < 32 * QN; i += 256) {
            int r = i >> 7, q = i & 127;       // QN = 128
            float4 v = __ldcg((const float4*)(hin + (size_t)r * HC + q * 4));
            *(float4*)&h4[(q * 33 + r) * 4] = v;
        }
        __syncthreads();

        float a00 = 0.f, a01 = 0.f, a10 = 0.f, a11 = 0.f;
        float a20 = 0.f, a21 = 0.f, a30 = 0.f, a31 = 0.f;
#pragma unroll 8
        for (int it = 0; it < HC / 16; it++) {
            float4 hv0 = *(const float4*)(hp0 + it * 132);
            float4 hv1 = *(const float4*)(hp1 + it * 132);
            float4 v0 = *(const float4*)(w0 + it * 4);
            float4 v1 = *(const float4*)(w1 + it * 4);
            float4 v2 = *(const float4*)(w2 + it * 4);
            float4 v3 = *(const float4*)(w3 + it * 4);
            a00 += hv0.x*v0.x + hv0.y*v0.y + hv0.z*v0.z + hv0.w*v0.w;
            a01 += hv1.x*v0.x + hv1.y*v0.y + hv1.z*v0.z + hv1.w*v0.w;
            a10 += hv0.x*v1.x + hv0.y*v1.y + hv0.z*v1.z + hv0.w*v1.w;
            a11 += hv1.x*v1.x + hv1.y*v1.y + hv1.z*v1.z + hv1.w*v1.w;
            a20 += hv0.x*v2.x + hv0.y*v2.y + hv0.z*v2.z + hv0.w*v2.w;
            a21 += hv1.x*v2.x + hv1.y*v2.y + hv1.z*v2.z + hv1.w*v2.w;
            a30 += hv0.x*v3.x + hv0.y*v3.y + hv0.z*v3.z + hv0.w*v3.w;
            a31 += hv1.x*v3.x + hv1.y*v3.y + hv1.z*v3.z + hv1.w*v3.w;
        }
        if (kq != 0) {
            float* rp = &red[((kq - 1) * 64 + cell) * 8];
            rp[0]=a00; rp[1]=a01; rp[2]=a10; rp[3]=a11;
            rp[4]=a20; rp[5]=a21; rp[6]=a30; rp[7]=a31;
        }
        __syncthreads();
        if (kq == 0) {
#pragma unroll
            for (int p = 0; p < 3; p++) {
                const float* rp = &red[(p * 64 + cell) * 8];
                a00+=rp[0]; a01+=rp[1]; a10+=rp[2]; a11+=rp[3];
                a20+=rp[4]; a21+=rp[5]; a30+=rp[6]; a31+=rp[7];
            }
#pragma unroll
            for (int j = 0; j < 2; j++) {
                float gi = xv0[j] + (j ? a01 : a00) + bi0;
                float gf = xv1[j] + (j ? a11 : a10) + bi1;
                float gg = xv2[j] + (j ? a21 : a20) + bi2;
                float go = xv3[j] + (j ? a31 : a30) + bi3;
                float ii = 1.f / (1.f + expf(-gi));
                float ff = 1.f / (1.f + expf(-gf));
                float oo = 1.f / (1.f + expf(-go));
                float cc = ff * (j ? c1 : c0) + ii * tanhf(gg);
                float hn = oo * tanhf(cc);
                if (j) c1 = cc; else c0 = cc;
                int b = bhalf * 32 + bg + j * 16;
                hbuf[(size_t)((s + 1) & 1) * (B_ * 512) + b * HC + ug] = hn;
                y[((size_t)s * B_ + b) * 512 + ug] = hn;
            }
        }
        if (s + 1 < T_) grid_bar();
    }
}

static inline void launch_gemm(const float* A, const float* W, const float* bias,
                               float* C, int M, int N) {
    dim3 g(N / 128, M / 128), bl(256);
    gemm_bias_kernel<<<g, bl>>>(A, W, bias, C, M, N);
}

extern "C" void kernel_launch(void* const* d_in, const int* in_sizes, int n_in,
                              void* d_out, int out_size) {
    (void)in_sizes; (void)n_in; (void)out_size;
    const int*   src      = (const int*)  d_in[0];
    const int*   tgt      = (const int*)  d_in[1];
    const float* src_emb  = (const float*)d_in[2];
    const float* tgt_emb  = (const float*)d_in[3];
    const float* enc_Wih  = (const float*)d_in[4];   // [2,2,1024,512]
    const float* enc_Whh  = (const float*)d_in[5];   // [2,2,1024,256]
    const float* enc_bih  = (const float*)d_in[6];   // [2,2,1024]
    const float* enc_bhh  = (const float*)d_in[7];   // [2,2,1024]
    const float* dec_Wih  = (const float*)d_in[8];   // [2,2048,512]
    const float* dec_Whh  = (const float*)d_in[9];   // [2,2048,512]
    const float* dec_bih  = (const float*)d_in[10];  // [2,2048]
    const float* dec_bhh  = (const float*)d_in[11];  // [2,2048]
    const float* lin_W    = (const float*)d_in[12];  // [32000,512]
    const float* lin_b    = (const float*)d_in[13];  // [32000]
    float* logits = (float*)d_out;

    float *xA, *xB, *hbuf, *hfA, *cfA, *xgA, *xgB, *xgD;
    cudaGetSymbolAddress((void**)&xA,   g_x);
    cudaGetSymbolAddress((void**)&xB,   g_y);
    cudaGetSymbolAddress((void**)&hbuf, g_hbuf);
    cudaGetSymbolAddress((void**)&hfA,  g_hf);
    cudaGetSymbolAddress((void**)&cfA,  g_cf);
    cudaGetSymbolAddress((void**)&xgA,  g_xgA);
    cudaGetSymbolAddress((void**)&xgB,  g_xgB);
    cudaGetSymbolAddress((void**)&xgD,  g_xgD);

    // smem: w 16*HC + h4 (HC/4)*33*4 + red 1536 floats
    const int SMEM_ENC = (16 * 256 + 64 * 33 * 4 + 1536) * 4;    // 56,320 B
    const int SMEM_DEC = (16 * 512 + 128 * 33 * 4 + 1536) * 4;   // 106,496 B
    cudaFuncSetAttribute(enc_seq_kernel, cudaFuncAttributeMaxDynamicSharedMemorySize, SMEM_ENC);
    cudaFuncSetAttribute(dec_seq_kernel, cudaFuncAttributeMaxDynamicSharedMemorySize, SMEM_DEC);

    // ---- source embedding ----
    embed_kernel<<<TB_, 128>>>(src, src_emb, xA);

    // ---- encoder: 2 stacked bidirectional layers ----
    float* ein = xA;
    float* eout = xB;
    for (int l = 0; l < 2; l++) {
        const float* Wih = enc_Wih + (size_t)l * 2 * 1024 * 512;
        const float* Whh = enc_Whh + (size_t)l * 2 * 1024 * 256;
        const float* bih = enc_bih + (size_t)l * 2 * 1024;
        const float* bhh = enc_bhh + (size_t)l * 2 * 1024;
        launch_gemm(ein, Wih,              bih,        xgA, TB_, 1024);
        launch_gemm(ein, Wih + 1024 * 512, bih + 1024, xgB, TB_, 1024);
        enc_seq_kernel<<<GRID_P, 256, SMEM_ENC>>>(
            xgA, xgB, Whh, bhh, hbuf, eout,
            hfA + (size_t)l * B_ * 512, cfA + (size_t)l * B_ * 512);
        float* tmp = ein; ein = eout; eout = tmp;
    }

    // ---- target embedding ----
    float* din = eout;
    float* dout = ein;
    embed_kernel<<<TB_, 128>>>(tgt, tgt_emb, din);

    // ---- decoder: 2 stacked layers, hidden 512 ----
    for (int l = 0; l < 2; l++) {
        const float* Wih = dec_Wih + (size_t)l * 2048 * 512;
        const float* Whh = dec_Whh + (size_t)l * 2048 * 512;
        const float* bih = dec_bih + (size_t)l * 2048;
        const float* bhh = dec_bhh + (size_t)l * 2048;
        launch_gemm(din, Wih, bih, xgD, TB_, 2048);
        dec_seq_kernel<<<GRID_P, 256, SMEM_DEC>>>(
            xgD, Whh, bhh,
            hfA + (size_t)l * B_ * 512, cfA + (size_t)l * B_ * 512,
            hbuf, dout);
        float* tmp = din; din = dout; dout = tmp;
    }

    // ---- final projection: logits[2560,32000] = y @ lin_W^T + lin_b ----
    launch_gemm(din, lin_W, lin_b, logits, TB_, 32000);
}